// round 14
// baseline (speedup 1.0000x reference)
#include <cuda_runtime.h>
#include <math_constants.h>
#include <cstdint>

#define LOG2E 1.4426950408889634f

// Scratch (no allocations allowed): per-(b,chunk) partial L and ctx[32],
// plus a per-batch arrival counter (reset to 0 by the last CTA each launch).
__device__ float g_pl[8192];
__device__ float g_pctx[8192 * 32];
__device__ int   g_cnt[2048];            // zero-initialized

// Non-volatile on purpose — pure register computation; ptxas schedules
// around the tensor-op latency.
__device__ __forceinline__ void mma_tf32(
    float& d0, float& d1, float& d2, float& d3,
    uint32_t a0, uint32_t a1, uint32_t a2, uint32_t a3,
    uint32_t b0, uint32_t b1)
{
    asm("mma.sync.aligned.m16n8k8.row.col.f32.tf32.tf32.f32 "
        "{%0,%1,%2,%3}, {%4,%5,%6,%7}, {%8,%9}, {%0,%1,%2,%3};"
        : "+f"(d0), "+f"(d1), "+f"(d2), "+f"(d3)
        : "r"(a0), "r"(a1), "r"(a2), "r"(a3), "r"(b0), "r"(b1));
}

__device__ __forceinline__ uint32_t tf32_rna(float x)
{
    uint32_t r;
    asm("cvt.rna.tf32.f32 %0, %1;" : "=r"(r) : "f"(x));
    return r;
}

// Stage one 32-row group (32 floats/row) into smem at row stride 36 floats.
__device__ __forceinline__
void stage_group(const float* __restrict__ gRowBase, int rowsLeft,
                 float* __restrict__ xb, int lane)
{
    const char* gsrc = (const char*)gRowBase;
    const int maxIdx = rowsLeft * 8 - 1;
    #pragma unroll
    for (int k = 0; k < 8; ++k) {
        const int idx = k * 32 + lane;               // 0..255 16B chunks
        const int row = idx >> 3, c = idx & 7;
        unsigned long long saddr =
            __cvta_generic_to_shared(xb + row * 36 + c * 4);
        const char* src = gsrc + (size_t)min(idx, maxIdx) * 16;
        asm volatile("cp.async.cg.shared.global [%0], [%1], 16;"
                     :: "l"(saddr), "l"(src));
    }
}

// ---------------------------------------------------------------------------
// Single kernel: grid (nChunk, B), 128 threads, 4 CTAs/SM. CTA covers 1024
// rows; warp sweeps 8 x 32-row groups, double-buffered cp.async. Keys GEMM:
// m16n8k8 tf32 single-pass (calibrated error ~1e-4 << 1e-3); tanh.approx.
// Unnormalized p -> out_w; the LAST CTA of each batch (atomic counter) merges
// the partials deterministically, writes context, and normalizes the row.
// ---------------------------------------------------------------------------
__global__ __launch_bounds__(128, 4)
void attn_main(const float* __restrict__ lstm, const float* __restrict__ fh,
               const float* __restrict__ Wq, const float* __restrict__ bq,
               const float* __restrict__ Wk, const float* __restrict__ bk,
               const float* __restrict__ Wv, const float* __restrict__ bv,
               float* __restrict__ out_ctx, float* __restrict__ out_w, int S)
{
    const int chunk = blockIdx.x;
    const int nCh   = gridDim.x;
    const int b     = blockIdx.y;
    const int tid   = threadIdx.x;
    const int w     = tid >> 5;
    const int lane  = tid & 31;
    const int g8    = lane >> 2;
    const int t4    = lane & 3;

    extern __shared__ __align__(16) float sX[];      // 4 warps * 2 * 1152

    __shared__ __align__(16) float sQC[32];
    __shared__ float sCtxW[128], sLw[4];
    __shared__ int sLast;

    float* xb0 = sX + w * 2304;                      // two 1152-float buffers
    const size_t rowB = (size_t)b * S;
    const int cbase = chunk * 1024;

    // ---- prefetch group 0 ----
    {
        const int base = cbase + w * 32;
        if (base < S)
            stage_group(lstm + (rowB + base) * 32, S - base, xb0, lane);
        asm volatile("cp.async.commit_group;");
    }

    // ---- prologue: query GEMV (overlaps group-0 DRAM latency) ----
    if (tid < 32) {
        float acc = bq[tid];
        #pragma unroll
        for (int h = 0; h < 32; ++h)
            acc = fmaf(fh[b * 32 + h], Wq[h * 32 + tid], acc);
        sQC[tid] = acc;
    }

    // ---- Wk fragments (tf32 rna): B[k][n] = Wk[k*32+n] ----
    uint32_t Bf[4][4][2];
    #pragma unroll
    for (int kt = 0; kt < 4; ++kt)
        #pragma unroll
        for (int nt = 0; nt < 4; ++nt) {
            const int n = nt * 8 + g8;
            Bf[kt][nt][0] = tf32_rna(Wk[(kt * 8 + t4) * 32 + n]);
            Bf[kt][nt][1] = tf32_rna(Wk[(kt * 8 + t4 + 4) * 32 + n]);
        }

    __syncthreads();

    // ---- per-lane column constants (slot s -> col = (s>>1)*8+2*t4+(s&1)) --
    float qbk[8], wvv[8];
    #pragma unroll
    for (int s = 0; s < 8; ++s) {
        const int col = (s >> 1) * 8 + 2 * t4 + (s & 1);
        wvv[s] = Wv[col];
        qbk[s] = sQC[col] + bk[col];
    }
    const float w1l = bv[0] * LOG2E;     // p = exp2(score*log2e + bv*log2e)

    float l = 0.f;
    float ctxD[8];
    #pragma unroll
    for (int s = 0; s < 8; ++s) ctxD[s] = 0.f;

    // ---- main sweep: 8 groups of 32 rows per warp ----
    #pragma unroll 1
    for (int gi = 0; gi < 8; ++gi) {
        if (gi + 1 < 8) {
            const int nb = cbase + (gi + 1) * 128 + w * 32;
            if (nb < S)
                stage_group(lstm + (rowB + nb) * 32, S - nb,
                            xb0 + ((gi + 1) & 1) * 1152, lane);
            asm volatile("cp.async.commit_group;");
            asm volatile("cp.async.wait_group 1;");
        } else {
            asm volatile("cp.async.wait_group 0;");
        }
        __syncwarp();

        const int gs = cbase + gi * 128 + w * 32;
        if (gs >= S) continue;
        const float* xg = xb0 + (gi & 1) * 1152;

        #pragma unroll 1
        for (int mt = 0; mt < 2; ++mt) {
            // ---- GEMM: D[16] = X[mt-tile] @ Wk (1-pass tf32) ----
            float D[16];
            #pragma unroll
            for (int e = 0; e < 16; ++e) D[e] = 0.f;

            #pragma unroll
            for (int kt = 0; kt < 4; ++kt) {
                const int abase = (mt * 16 + g8) * 36 + kt * 8 + t4;
                uint32_t a0 = tf32_rna(xg[abase]);
                uint32_t a1 = tf32_rna(xg[abase + 288]);   // +8 rows
                uint32_t a2 = tf32_rna(xg[abase + 4]);     // +4 k
                uint32_t a3 = tf32_rna(xg[abase + 292]);

                #pragma unroll
                for (int nt = 0; nt < 4; ++nt)
                    mma_tf32(D[nt * 4], D[nt * 4 + 1], D[nt * 4 + 2],
                             D[nt * 4 + 3], a0, a1, a2, a3,
                             Bf[kt][nt][0], Bf[kt][nt][1]);
            }

            // ---- epilogue: rows r0 = gs+mt*16+g8, r1 = r0+8 ----
            const int r0 = gs + mt * 16 + g8;
            const int r1 = r0 + 8;
            const bool v0 = r0 < S, v1 = r1 < S;

            float s0 = 0.f, s1 = 0.f;
            #pragma unroll
            for (int nt = 0; nt < 4; ++nt)
                #pragma unroll
                for (int c = 0; c < 4; ++c) {
                    const int e = nt * 4 + c;
                    const int s = nt * 2 + (c & 1);
                    float t;                          // HW tanh: 1 MUFU op
                    asm("tanh.approx.f32 %0, %1;"
                        : "=f"(t) : "f"(D[e] + qbk[s]));
                    if (c < 2) s0 = fmaf(t, wvv[s], s0);
                    else       s1 = fmaf(t, wvv[s], s1);
                }

            s0 += __shfl_xor_sync(0xffffffffu, s0, 1);
            s0 += __shfl_xor_sync(0xffffffffu, s0, 2);
            s1 += __shfl_xor_sync(0xffffffffu, s1, 1);
            s1 += __shfl_xor_sync(0xffffffffu, s1, 2);

            float p0, p1;
            asm("ex2.approx.f32 %0, %1;" : "=f"(p0)
                : "f"(fmaf(s0, LOG2E, w1l)));
            asm("ex2.approx.f32 %0, %1;" : "=f"(p1)
                : "f"(fmaf(s1, LOG2E, w1l)));
            if (!v0) p0 = 0.f;
            if (!v1) p1 = 0.f;

            if (t4 == 0) {                           // unnormalized p -> gmem
                if (v0) out_w[rowB + r0] = p0;
                if (v1) out_w[rowB + r1] = p1;
            }

            l += p0 + p1;
            #pragma unroll
            for (int nt = 0; nt < 4; ++nt)
                #pragma unroll
                for (int bit = 0; bit < 2; ++bit) {
                    const int s = nt * 2 + bit;
                    ctxD[s] = fmaf(p0, D[nt * 4 + bit],
                              fmaf(p1, D[nt * 4 + 2 + bit], ctxD[s]));
                }
        }
    }

    // ---- warp reduce: l (/4 quad dup) and ctxD ----
    #pragma unroll
    for (int off = 16; off; off >>= 1)
        l += __shfl_xor_sync(0xffffffffu, l, off);
    l *= 0.25f;

    #pragma unroll
    for (int s = 0; s < 8; ++s) {
        ctxD[s] += __shfl_xor_sync(0xffffffffu, ctxD[s], 4);
        ctxD[s] += __shfl_xor_sync(0xffffffffu, ctxD[s], 8);
        ctxD[s] += __shfl_xor_sync(0xffffffffu, ctxD[s], 16);
    }
    if (g8 == 0) {
        #pragma unroll
        for (int s = 0; s < 8; ++s) {
            const int col = (s >> 1) * 8 + 2 * t4 + (s & 1);
            sCtxW[w * 32 + col] = ctxD[s];
        }
    }
    if (lane == 0) sLw[w] = l;
    __syncthreads();

    // ---- per-CTA partial out (deterministic per-chunk slots) ----
    if (tid < 32) {
        float L = 0.f, ct = 0.f;
        #pragma unroll
        for (int ww = 0; ww < 4; ++ww) {
            L  += sLw[ww];
            ct += sCtxW[ww * 32 + tid];
        }
        const int pc = b * nCh + chunk;
        g_pctx[pc * 32 + tid] = ct;
        if (tid == 0) g_pl[pc] = L;
    }

    // ---- last-CTA-of-batch finish: merge, context, normalize ----
    __threadfence();                       // partials + p stores visible
    if (tid == 0) {
        const int old = atomicAdd(&g_cnt[b], 1);
        sLast = (old == nCh - 1) ? 1 : 0;
    }
    __syncthreads();
    if (sLast) {
        __threadfence();                   // acquire prior CTAs' writes

        float L = 0.f;
        for (int c = 0; c < nCh; ++c) L += g_pl[b * nCh + c];   // fixed order
        const float inv = 1.f / L;

        if (tid < 32) {
            float ct = 0.f;
            for (int c = 0; c < nCh; ++c)
                ct += g_pctx[(b * nCh + c) * 32 + tid];
            out_ctx[b * 32 + tid] = fmaf(ct, inv, bk[tid]);     // + bk fold
        }

        float4* p4 = (float4*)(out_w + rowB);
        const int nF4 = S >> 2;
        for (int i = tid; i < nF4; i += 128) {
            float4 v = p4[i];
            v.x *= inv; v.y *= inv; v.z *= inv; v.w *= inv;
            p4[i] = v;
        }
        for (int i = (nF4 << 2) + tid; i < S; i += 128)
            out_w[rowB + i] *= inv;

        __syncthreads();
        if (tid == 0) g_cnt[b] = 0;        // reset for next graph replay
    }
}

// ---------------------------------------------------------------------------
extern "C" void kernel_launch(void* const* d_in, const int* in_sizes, int n_in,
                              void* d_out, int out_size)
{
    const float* lstm = (const float*)d_in[0];
    const float* fh   = (const float*)d_in[1];
    const float* Wq   = (const float*)d_in[2];
    const float* bq   = (const float*)d_in[3];
    const float* Wk   = (const float*)d_in[4];
    const float* bk   = (const float*)d_in[5];
    const float* Wv   = (const float*)d_in[6];
    const float* bv   = (const float*)d_in[7];

    const int BH = in_sizes[1];            // B * H
    const int B  = BH / 32;
    const int S  = in_sizes[0] / BH;
    const int nCh = (S + 1023) / 1024;     // 1024 rows per CTA

    float* out_ctx = (float*)d_out;                 // [B, 32]
    float* out_w   = out_ctx + (size_t)B * 32;      // [B, S]

    const int smemBytes = 4 * 2304 * (int)sizeof(float);   // 36 KB
    static int attrSet = 0;
    if (!attrSet) {
        cudaFuncSetAttribute(attn_main,
                             cudaFuncAttributeMaxDynamicSharedMemorySize,
                             smemBytes);
        attrSet = 1;
    }

    dim3 grid(nCh, B);
    attn_main<<<grid, 128, smemBytes>>>(lstm, fh, Wq, bq, Wk, bk, Wv, bv,
                                        out_ctx, out_w, S);
}

// round 15
// speedup vs baseline: 1.0608x; 1.0608x over previous
#include <cuda_runtime.h>
#include <math_constants.h>
#include <cstdint>

#define LOG2E 1.4426950408889634f

// Scratch (no allocations allowed): per-(b,chunk) partial L and ctx[32].
__device__ __align__(16) float g_pl[8192];
__device__ float g_pctx[8192 * 32];

// Non-volatile on purpose — pure register computation; ptxas schedules
// around the tensor-op latency.
__device__ __forceinline__ void mma_tf32(
    float& d0, float& d1, float& d2, float& d3,
    uint32_t a0, uint32_t a1, uint32_t a2, uint32_t a3,
    uint32_t b0, uint32_t b1)
{
    asm("mma.sync.aligned.m16n8k8.row.col.f32.tf32.tf32.f32 "
        "{%0,%1,%2,%3}, {%4,%5,%6,%7}, {%8,%9}, {%0,%1,%2,%3};"
        : "+f"(d0), "+f"(d1), "+f"(d2), "+f"(d3)
        : "r"(a0), "r"(a1), "r"(a2), "r"(a3), "r"(b0), "r"(b1));
}

__device__ __forceinline__ uint32_t tf32_rna(float x)
{
    uint32_t r;
    asm("cvt.rna.tf32.f32 %0, %1;" : "=r"(r) : "f"(x));
    return r;
}

// Stage one 32-row group (32 floats/row) into smem at row stride 36 floats.
__device__ __forceinline__
void stage_group(const float* __restrict__ gRowBase, int rowsLeft,
                 float* __restrict__ xb, int lane)
{
    const char* gsrc = (const char*)gRowBase;
    const int maxIdx = rowsLeft * 8 - 1;
    #pragma unroll
    for (int k = 0; k < 8; ++k) {
        const int idx = k * 32 + lane;               // 0..255 16B chunks
        const int row = idx >> 3, c = idx & 7;
        unsigned long long saddr =
            __cvta_generic_to_shared(xb + row * 36 + c * 4);
        const char* src = gsrc + (size_t)min(idx, maxIdx) * 16;
        asm volatile("cp.async.cg.shared.global [%0], [%1], 16;"
                     :: "l"(saddr), "l"(src));
    }
}

// ---------------------------------------------------------------------------
// Kernel 1: grid (nChunk, B), 128 threads, 4 CTAs/SM (54 KB smem each).
// CTA covers 1024 rows; warp sweeps 8 x 32-row groups with a 3-stage
// cp.async pipeline (2 groups always in flight). Keys GEMM: m16n8k8 tf32
// single-pass; tanh.approx score; unnormalized p -> out_w.
// ---------------------------------------------------------------------------
__global__ __launch_bounds__(128, 4)
void attn_main(const float* __restrict__ lstm, const float* __restrict__ fh,
               const float* __restrict__ Wq, const float* __restrict__ bq,
               const float* __restrict__ Wk, const float* __restrict__ bk,
               const float* __restrict__ Wv, const float* __restrict__ bv,
               float* __restrict__ out_w, int S)
{
    const int chunk = blockIdx.x;
    const int b     = blockIdx.y;
    const int tid   = threadIdx.x;
    const int w     = tid >> 5;
    const int lane  = tid & 31;
    const int g8    = lane >> 2;
    const int t4    = lane & 3;

    extern __shared__ __align__(16) float sX[];      // 4 warps * 3 * 1152

    __shared__ __align__(16) float sQC[32];
    __shared__ float sCtxW[128], sLw[4];

    float* xb0 = sX + w * 3456;                      // three 1152-float bufs
    const size_t rowB = (size_t)b * S;
    const int cbase = chunk * 1024;

    // ---- prefetch groups 0 and 1 ----
    {
        const int b0 = cbase + w * 32;
        if (b0 < S)
            stage_group(lstm + (rowB + b0) * 32, S - b0, xb0, lane);
        asm volatile("cp.async.commit_group;");
        const int b1 = cbase + 128 + w * 32;
        if (b1 < S)
            stage_group(lstm + (rowB + b1) * 32, S - b1, xb0 + 1152, lane);
        asm volatile("cp.async.commit_group;");
    }

    // ---- prologue: query GEMV (overlaps prefetch DRAM latency) ----
    if (tid < 32) {
        float acc = bq[tid];
        #pragma unroll
        for (int h = 0; h < 32; ++h)
            acc = fmaf(fh[b * 32 + h], Wq[h * 32 + tid], acc);
        sQC[tid] = acc;
    }

    // ---- Wk fragments (tf32 rna): B[k][n] = Wk[k*32+n] ----
    uint32_t Bf[4][4][2];
    #pragma unroll
    for (int kt = 0; kt < 4; ++kt)
        #pragma unroll
        for (int nt = 0; nt < 4; ++nt) {
            const int n = nt * 8 + g8;
            Bf[kt][nt][0] = tf32_rna(Wk[(kt * 8 + t4) * 32 + n]);
            Bf[kt][nt][1] = tf32_rna(Wk[(kt * 8 + t4 + 4) * 32 + n]);
        }

    __syncthreads();

    // ---- per-lane column constants (slot s -> col = (s>>1)*8+2*t4+(s&1)) --
    float qbk[8], wvv[8];
    #pragma unroll
    for (int s = 0; s < 8; ++s) {
        const int col = (s >> 1) * 8 + 2 * t4 + (s & 1);
        wvv[s] = Wv[col];
        qbk[s] = sQC[col] + bk[col];
    }
    const float w1l = bv[0] * LOG2E;     // p = exp2(score*log2e + bv*log2e)

    float l = 0.f;
    float ctxD[8];
    #pragma unroll
    for (int s = 0; s < 8; ++s) ctxD[s] = 0.f;

    // ---- main sweep: 8 groups of 32 rows per warp, 3-stage pipeline ----
    #pragma unroll 1
    for (int gi = 0; gi < 8; ++gi) {
        if (gi + 2 < 8) {
            const int nb = cbase + (gi + 2) * 128 + w * 32;
            if (nb < S)
                stage_group(lstm + (rowB + nb) * 32, S - nb,
                            xb0 + ((gi + 2) % 3) * 1152, lane);
            asm volatile("cp.async.commit_group;");
            asm volatile("cp.async.wait_group 2;");
        } else if (gi + 1 < 8) {
            asm volatile("cp.async.wait_group 1;");
        } else {
            asm volatile("cp.async.wait_group 0;");
        }
        __syncwarp();

        const int gs = cbase + gi * 128 + w * 32;
        if (gs >= S) continue;
        const float* xg = xb0 + (gi % 3) * 1152;

        #pragma unroll 1
        for (int mt = 0; mt < 2; ++mt) {
            // ---- GEMM: D[16] = X[mt-tile] @ Wk (1-pass tf32) ----
            float D[16];
            #pragma unroll
            for (int e = 0; e < 16; ++e) D[e] = 0.f;

            #pragma unroll
            for (int kt = 0; kt < 4; ++kt) {
                const int abase = (mt * 16 + g8) * 36 + kt * 8 + t4;
                uint32_t a0 = tf32_rna(xg[abase]);
                uint32_t a1 = tf32_rna(xg[abase + 288]);   // +8 rows
                uint32_t a2 = tf32_rna(xg[abase + 4]);     // +4 k
                uint32_t a3 = tf32_rna(xg[abase + 292]);

                #pragma unroll
                for (int nt = 0; nt < 4; ++nt)
                    mma_tf32(D[nt * 4], D[nt * 4 + 1], D[nt * 4 + 2],
                             D[nt * 4 + 3], a0, a1, a2, a3,
                             Bf[kt][nt][0], Bf[kt][nt][1]);
            }

            // ---- epilogue: rows r0 = gs+mt*16+g8, r1 = r0+8 ----
            const int r0 = gs + mt * 16 + g8;
            const int r1 = r0 + 8;
            const bool v0 = r0 < S, v1 = r1 < S;

            float s0 = 0.f, s1 = 0.f;
            #pragma unroll
            for (int nt = 0; nt < 4; ++nt)
                #pragma unroll
                for (int c = 0; c < 4; ++c) {
                    const int e = nt * 4 + c;
                    const int s = nt * 2 + (c & 1);
                    float t;                          // HW tanh: 1 MUFU op
                    asm("tanh.approx.f32 %0, %1;"
                        : "=f"(t) : "f"(D[e] + qbk[s]));
                    if (c < 2) s0 = fmaf(t, wvv[s], s0);
                    else       s1 = fmaf(t, wvv[s], s1);
                }

            s0 += __shfl_xor_sync(0xffffffffu, s0, 1);
            s0 += __shfl_xor_sync(0xffffffffu, s0, 2);
            s1 += __shfl_xor_sync(0xffffffffu, s1, 1);
            s1 += __shfl_xor_sync(0xffffffffu, s1, 2);

            float p0, p1;
            asm("ex2.approx.f32 %0, %1;" : "=f"(p0)
                : "f"(fmaf(s0, LOG2E, w1l)));
            asm("ex2.approx.f32 %0, %1;" : "=f"(p1)
                : "f"(fmaf(s1, LOG2E, w1l)));
            if (!v0) p0 = 0.f;
            if (!v1) p1 = 0.f;

            if (t4 == 0) {                           // unnormalized p -> gmem
                if (v0) out_w[rowB + r0] = p0;
                if (v1) out_w[rowB + r1] = p1;
            }

            l += p0 + p1;
            #pragma unroll
            for (int nt = 0; nt < 4; ++nt)
                #pragma unroll
                for (int bit = 0; bit < 2; ++bit) {
                    const int s = nt * 2 + bit;
                    ctxD[s] = fmaf(p0, D[nt * 4 + bit],
                              fmaf(p1, D[nt * 4 + 2 + bit], ctxD[s]));
                }
        }
    }

    // ---- warp reduce: l (/4 quad dup) and ctxD ----
    #pragma unroll
    for (int off = 16; off; off >>= 1)
        l += __shfl_xor_sync(0xffffffffu, l, off);
    l *= 0.25f;

    #pragma unroll
    for (int s = 0; s < 8; ++s) {
        ctxD[s] += __shfl_xor_sync(0xffffffffu, ctxD[s], 4);
        ctxD[s] += __shfl_xor_sync(0xffffffffu, ctxD[s], 8);
        ctxD[s] += __shfl_xor_sync(0xffffffffu, ctxD[s], 16);
    }
    if (g8 == 0) {
        #pragma unroll
        for (int s = 0; s < 8; ++s) {
            const int col = (s >> 1) * 8 + 2 * t4 + (s & 1);
            sCtxW[w * 32 + col] = ctxD[s];
        }
    }
    if (lane == 0) sLw[w] = l;
    __syncthreads();

    // ---- per-CTA partial out ----
    if (tid < 32) {
        float L = 0.f, ct = 0.f;
        #pragma unroll
        for (int ww = 0; ww < 4; ++ww) {
            L  += sLw[ww];
            ct += sCtxW[ww * 32 + tid];
        }
        const int pc = b * gridDim.x + chunk;
        g_pctx[pc * 32 + tid] = ct;
        if (tid == 0) g_pl[pc] = L;
    }
}

// ---------------------------------------------------------------------------
// Kernel 2 (finish): L from ONE float4 load of the 4 chunk partials;
// block x==0 merges ctx. weights = p * (1/L), one float4 per thread.
// Grid (ceil(S/1024), B), 256 threads.
// ---------------------------------------------------------------------------
__global__ __launch_bounds__(256)
void attn_norm(const float* __restrict__ bk, float* __restrict__ out_ctx,
               float* __restrict__ out_w, int S, int nCh)
{
    const int b   = blockIdx.y;
    const int tid = threadIdx.x;

    float L;
    if (nCh == 4) {                        // fast path: single LDG.128
        const float4 pl = *(const float4*)&g_pl[b * 4];
        L = (pl.x + pl.y) + (pl.z + pl.w);
    } else {
        L = 0.f;
        for (int c = 0; c < nCh; ++c) L += g_pl[b * nCh + c];
    }
    const float inv = 1.f / L;

    if (blockIdx.x == 0 && tid < 32) {
        float ct = 0.f;
        for (int c = 0; c < nCh; ++c)
            ct += g_pctx[(b * nCh + c) * 32 + tid];
        out_ctx[b * 32 + tid] = fmaf(ct, inv, bk[tid]);   // + bk fold
    }

    float* base = out_w + (size_t)b * S;
    const int nF4 = S >> 2;
    const int i = blockIdx.x * 256 + tid;
    if (i < nF4) {
        float4* p4 = (float4*)base + i;
        float4 v = *p4;
        v.x *= inv; v.y *= inv; v.z *= inv; v.w *= inv;
        *p4 = v;
    }
    // scalar tail (S not multiple of 4)
    for (int j = (nF4 << 2) + blockIdx.x * 256 + tid; j < S;
         j += gridDim.x * 256)
        base[j] *= inv;
}

// ---------------------------------------------------------------------------
extern "C" void kernel_launch(void* const* d_in, const int* in_sizes, int n_in,
                              void* d_out, int out_size)
{
    const float* lstm = (const float*)d_in[0];
    const float* fh   = (const float*)d_in[1];
    const float* Wq   = (const float*)d_in[2];
    const float* bq   = (const float*)d_in[3];
    const float* Wk   = (const float*)d_in[4];
    const float* bk   = (const float*)d_in[5];
    const float* Wv   = (const float*)d_in[6];
    const float* bv   = (const float*)d_in[7];

    const int BH = in_sizes[1];            // B * H
    const int B  = BH / 32;
    const int S  = in_sizes[0] / BH;
    const int nCh = (S + 1023) / 1024;     // 1024 rows per CTA

    float* out_ctx = (float*)d_out;                 // [B, 32]
    float* out_w   = out_ctx + (size_t)B * 32;      // [B, S]

    const int smemBytes = 4 * 3456 * (int)sizeof(float);   // 54 KB
    static int attrSet = 0;
    if (!attrSet) {
        cudaFuncSetAttribute(attn_main,
                             cudaFuncAttributeMaxDynamicSharedMemorySize,
                             smemBytes);
        attrSet = 1;
    }

    dim3 grid(nCh, B);
    attn_main<<<grid, 128, smemBytes>>>(lstm, fh, Wq, bq, Wk, bk, Wv, bv,
                                        out_w, S);

    dim3 ngrid((S / 4 + 255) / 256, B);
    attn_norm<<<ngrid, 256>>>(bk, out_ctx, out_w, S, nCh);
}

// round 16
// speedup vs baseline: 1.0774x; 1.0157x over previous
#include <cuda_runtime.h>
#include <math_constants.h>
#include <cstdint>

#define LOG2E 1.4426950408889634f

// Scratch (no allocations allowed): per-(b,chunk) partial L and ctx[32].
__device__ __align__(16) float g_pl[8192];
__device__ float g_pctx[8192 * 32];

// Non-volatile on purpose — pure register computation; ptxas schedules
// around the tensor-op latency.
__device__ __forceinline__ void mma_tf32(
    float& d0, float& d1, float& d2, float& d3,
    uint32_t a0, uint32_t a1, uint32_t a2, uint32_t a3,
    uint32_t b0, uint32_t b1)
{
    asm("mma.sync.aligned.m16n8k8.row.col.f32.tf32.tf32.f32 "
        "{%0,%1,%2,%3}, {%4,%5,%6,%7}, {%8,%9}, {%0,%1,%2,%3};"
        : "+f"(d0), "+f"(d1), "+f"(d2), "+f"(d3)
        : "r"(a0), "r"(a1), "r"(a2), "r"(a3), "r"(b0), "r"(b1));
}

__device__ __forceinline__ uint32_t tf32_rna(float x)
{
    uint32_t r;
    asm("cvt.rna.tf32.f32 %0, %1;" : "=r"(r) : "f"(x));
    return r;
}

// Stage one 32-row group (32 floats/row) into smem at row stride 36 floats.
__device__ __forceinline__
void stage_group(const float* __restrict__ gRowBase, int rowsLeft,
                 float* __restrict__ xb, int lane)
{
    const char* gsrc = (const char*)gRowBase;
    const int maxIdx = rowsLeft * 8 - 1;
    #pragma unroll
    for (int k = 0; k < 8; ++k) {
        const int idx = k * 32 + lane;               // 0..255 16B chunks
        const int row = idx >> 3, c = idx & 7;
        unsigned long long saddr =
            __cvta_generic_to_shared(xb + row * 36 + c * 4);
        const char* src = gsrc + (size_t)min(idx, maxIdx) * 16;
        asm volatile("cp.async.cg.shared.global [%0], [%1], 16;"
                     :: "l"(saddr), "l"(src));
    }
}

// ---------------------------------------------------------------------------
// Kernel 1 (R13 structure): grid (nChunk, B), 128 threads, 4 CTAs/SM
// (36 KB smem each -> 84 KB L1 left). CTA covers 1024 rows; warp sweeps
// 8 x 32-row groups, double-buffered cp.async. Keys GEMM: m16n8k8 tf32
// single-pass; tanh.approx score; unnormalized p -> out_w.
// ---------------------------------------------------------------------------
__global__ __launch_bounds__(128, 4)
void attn_main(const float* __restrict__ lstm, const float* __restrict__ fh,
               const float* __restrict__ Wq, const float* __restrict__ bq,
               const float* __restrict__ Wk, const float* __restrict__ bk,
               const float* __restrict__ Wv, const float* __restrict__ bv,
               float* __restrict__ out_w, int S)
{
    const int chunk = blockIdx.x;
    const int b     = blockIdx.y;
    const int tid   = threadIdx.x;
    const int w     = tid >> 5;
    const int lane  = tid & 31;
    const int g8    = lane >> 2;
    const int t4    = lane & 3;

    extern __shared__ __align__(16) float sX[];      // 4 warps * 2 * 1152

    __shared__ __align__(16) float sQC[32];
    __shared__ float sCtxW[128], sLw[4];

    float* xb0 = sX + w * 2304;                      // two 1152-float buffers
    const size_t rowB = (size_t)b * S;
    const int cbase = chunk * 1024;

    // ---- prefetch group 0 ----
    {
        const int base = cbase + w * 32;
        if (base < S)
            stage_group(lstm + (rowB + base) * 32, S - base, xb0, lane);
        asm volatile("cp.async.commit_group;");
    }

    // ---- prologue: query GEMV (overlaps group-0 DRAM latency) ----
    if (tid < 32) {
        float acc = bq[tid];
        #pragma unroll
        for (int h = 0; h < 32; ++h)
            acc = fmaf(fh[b * 32 + h], Wq[h * 32 + tid], acc);
        sQC[tid] = acc;
    }

    // ---- Wk fragments (tf32 rna): B[k][n] = Wk[k*32+n] ----
    uint32_t Bf[4][4][2];
    #pragma unroll
    for (int kt = 0; kt < 4; ++kt)
        #pragma unroll
        for (int nt = 0; nt < 4; ++nt) {
            const int n = nt * 8 + g8;
            Bf[kt][nt][0] = tf32_rna(Wk[(kt * 8 + t4) * 32 + n]);
            Bf[kt][nt][1] = tf32_rna(Wk[(kt * 8 + t4 + 4) * 32 + n]);
        }

    __syncthreads();

    // ---- per-lane column constants (slot s -> col = (s>>1)*8+2*t4+(s&1)) --
    float qbk[8], wvv[8];
    #pragma unroll
    for (int s = 0; s < 8; ++s) {
        const int col = (s >> 1) * 8 + 2 * t4 + (s & 1);
        wvv[s] = Wv[col];
        qbk[s] = sQC[col] + bk[col];
    }
    const float w1l = bv[0] * LOG2E;     // p = exp2(score*log2e + bv*log2e)

    float l = 0.f;
    float ctxD[8];
    #pragma unroll
    for (int s = 0; s < 8; ++s) ctxD[s] = 0.f;

    // ---- main sweep: 8 groups of 32 rows per warp ----
    #pragma unroll 1
    for (int gi = 0; gi < 8; ++gi) {
        if (gi + 1 < 8) {
            const int nb = cbase + (gi + 1) * 128 + w * 32;
            if (nb < S)
                stage_group(lstm + (rowB + nb) * 32, S - nb,
                            xb0 + ((gi + 1) & 1) * 1152, lane);
            asm volatile("cp.async.commit_group;");
            asm volatile("cp.async.wait_group 1;");
        } else {
            asm volatile("cp.async.wait_group 0;");
        }
        __syncwarp();

        const int gs = cbase + gi * 128 + w * 32;
        if (gs >= S) continue;
        const float* xg = xb0 + (gi & 1) * 1152;

        #pragma unroll 1
        for (int mt = 0; mt < 2; ++mt) {
            // ---- GEMM: D[16] = X[mt-tile] @ Wk (1-pass tf32) ----
            float D[16];
            #pragma unroll
            for (int e = 0; e < 16; ++e) D[e] = 0.f;

            #pragma unroll
            for (int kt = 0; kt < 4; ++kt) {
                const int abase = (mt * 16 + g8) * 36 + kt * 8 + t4;
                uint32_t a0 = tf32_rna(xg[abase]);
                uint32_t a1 = tf32_rna(xg[abase + 288]);   // +8 rows
                uint32_t a2 = tf32_rna(xg[abase + 4]);     // +4 k
                uint32_t a3 = tf32_rna(xg[abase + 292]);

                #pragma unroll
                for (int nt = 0; nt < 4; ++nt)
                    mma_tf32(D[nt * 4], D[nt * 4 + 1], D[nt * 4 + 2],
                             D[nt * 4 + 3], a0, a1, a2, a3,
                             Bf[kt][nt][0], Bf[kt][nt][1]);
            }

            // ---- epilogue: rows r0 = gs+mt*16+g8, r1 = r0+8 ----
            const int r0 = gs + mt * 16 + g8;
            const int r1 = r0 + 8;
            const bool v0 = r0 < S, v1 = r1 < S;

            float s0 = 0.f, s1 = 0.f;
            #pragma unroll
            for (int nt = 0; nt < 4; ++nt)
                #pragma unroll
                for (int c = 0; c < 4; ++c) {
                    const int e = nt * 4 + c;
                    const int s = nt * 2 + (c & 1);
                    float t;                          // HW tanh: 1 MUFU op
                    asm("tanh.approx.f32 %0, %1;"
                        : "=f"(t) : "f"(D[e] + qbk[s]));
                    if (c < 2) s0 = fmaf(t, wvv[s], s0);
                    else       s1 = fmaf(t, wvv[s], s1);
                }

            s0 += __shfl_xor_sync(0xffffffffu, s0, 1);
            s0 += __shfl_xor_sync(0xffffffffu, s0, 2);
            s1 += __shfl_xor_sync(0xffffffffu, s1, 1);
            s1 += __shfl_xor_sync(0xffffffffu, s1, 2);

            float p0, p1;
            asm("ex2.approx.f32 %0, %1;" : "=f"(p0)
                : "f"(fmaf(s0, LOG2E, w1l)));
            asm("ex2.approx.f32 %0, %1;" : "=f"(p1)
                : "f"(fmaf(s1, LOG2E, w1l)));
            if (!v0) p0 = 0.f;
            if (!v1) p1 = 0.f;

            if (t4 == 0) {                           // unnormalized p -> gmem
                if (v0) out_w[rowB + r0] = p0;
                if (v1) out_w[rowB + r1] = p1;
            }

            l += p0 + p1;
            #pragma unroll
            for (int nt = 0; nt < 4; ++nt)
                #pragma unroll
                for (int bit = 0; bit < 2; ++bit) {
                    const int s = nt * 2 + bit;
                    ctxD[s] = fmaf(p0, D[nt * 4 + bit],
                              fmaf(p1, D[nt * 4 + 2 + bit], ctxD[s]));
                }
        }
    }

    // ---- warp reduce: l (/4 quad dup) and ctxD ----
    #pragma unroll
    for (int off = 16; off; off >>= 1)
        l += __shfl_xor_sync(0xffffffffu, l, off);
    l *= 0.25f;

    #pragma unroll
    for (int s = 0; s < 8; ++s) {
        ctxD[s] += __shfl_xor_sync(0xffffffffu, ctxD[s], 4);
        ctxD[s] += __shfl_xor_sync(0xffffffffu, ctxD[s], 8);
        ctxD[s] += __shfl_xor_sync(0xffffffffu, ctxD[s], 16);
    }
    if (g8 == 0) {
        #pragma unroll
        for (int s = 0; s < 8; ++s) {
            const int col = (s >> 1) * 8 + 2 * t4 + (s & 1);
            sCtxW[w * 32 + col] = ctxD[s];
        }
    }
    if (lane == 0) sLw[w] = l;
    __syncthreads();

    // ---- per-CTA partial out ----
    if (tid < 32) {
        float L = 0.f, ct = 0.f;
        #pragma unroll
        for (int ww = 0; ww < 4; ++ww) {
            L  += sLw[ww];
            ct += sCtxW[ww * 32 + tid];
        }
        const int pc = b * gridDim.x + chunk;
        g_pctx[pc * 32 + tid] = ct;
        if (tid == 0) g_pl[pc] = L;
    }
}

// ---------------------------------------------------------------------------
// Kernel 2 (finish, PDL secondary): pre-launches during attn_main's tail
// wave; cudaGridDependencySynchronize() gates the data reads. Block x==0
// merges ctx; weights = p * (1/L), two float4 per thread.
// ---------------------------------------------------------------------------
__global__ __launch_bounds__(256)
void attn_norm(const float* __restrict__ bk, float* __restrict__ out_ctx,
               float* __restrict__ out_w, int S, int nCh)
{
    const int b   = blockIdx.y;
    const int tid = threadIdx.x;
    float* base = out_w + (size_t)b * S;
    const int nF4 = S >> 2;
    const int i0 = blockIdx.x * 512 + tid;

    // Wait for attn_main's writes (PDL edge); address math above overlaps.
    cudaGridDependencySynchronize();

    float L;
    if (nCh == 4) {                        // fast path: single LDG.128
        const float4 pl = *(const float4*)&g_pl[b * 4];
        L = (pl.x + pl.y) + (pl.z + pl.w);
    } else {
        L = 0.f;
        for (int c = 0; c < nCh; ++c) L += g_pl[b * nCh + c];
    }
    const float inv = 1.f / L;

    if (blockIdx.x == 0 && tid < 32) {
        float ct = 0.f;
        for (int c = 0; c < nCh; ++c)
            ct += g_pctx[(b * nCh + c) * 32 + tid];
        out_ctx[b * 32 + tid] = fmaf(ct, inv, bk[tid]);   // + bk fold
    }

    float4* p4 = (float4*)base;
    #pragma unroll
    for (int rep = 0; rep < 2; ++rep) {
        const int i = i0 + rep * 256;
        if (i < nF4) {
            float4 v = p4[i];
            v.x *= inv; v.y *= inv; v.z *= inv; v.w *= inv;
            p4[i] = v;
        }
    }
    for (int j = (nF4 << 2) + blockIdx.x * 256 + tid; j < S;
         j += gridDim.x * 256)
        base[j] *= inv;
}

// ---------------------------------------------------------------------------
extern "C" void kernel_launch(void* const* d_in, const int* in_sizes, int n_in,
                              void* d_out, int out_size)
{
    const float* lstm = (const float*)d_in[0];
    const float* fh   = (const float*)d_in[1];
    const float* Wq   = (const float*)d_in[2];
    const float* bq   = (const float*)d_in[3];
    const float* Wk   = (const float*)d_in[4];
    const float* bk   = (const float*)d_in[5];
    const float* Wv   = (const float*)d_in[6];
    const float* bv   = (const float*)d_in[7];

    const int BH = in_sizes[1];            // B * H
    const int B  = BH / 32;
    const int S  = in_sizes[0] / BH;
    const int nCh = (S + 1023) / 1024;     // 1024 rows per CTA

    float* out_ctx = (float*)d_out;                 // [B, 32]
    float* out_w   = out_ctx + (size_t)B * 32;      // [B, S]

    const int smemBytes = 4 * 2304 * (int)sizeof(float);   // 36 KB
    static int attrSet = 0;
    if (!attrSet) {
        cudaFuncSetAttribute(attn_main,
                             cudaFuncAttributeMaxDynamicSharedMemorySize,
                             smemBytes);
        attrSet = 1;
    }

    dim3 grid(nCh, B);
    attn_main<<<grid, 128, smemBytes>>>(lstm, fh, Wq, bq, Wk, bk, Wv, bv,
                                        out_w, S);

    // PDL launch of the finish kernel: pre-launch during main's tail wave.
    cudaLaunchConfig_t cfg = {};
    cfg.gridDim  = dim3((S / 4 + 511) / 512, B);
    cfg.blockDim = dim3(256);
    cfg.dynamicSmemBytes = 0;
    cfg.stream = 0;
    cudaLaunchAttribute attrs[1];
    attrs[0].id = cudaLaunchAttributeProgrammaticStreamSerialization;
    attrs[0].val.programmaticStreamSerializationAllowed = 1;
    cfg.attrs = attrs;
    cfg.numAttrs = 1;
    cudaLaunchKernelEx(&cfg, attn_norm, bk, out_ctx, out_w, S, nCh);
}